// round 15
// baseline (speedup 1.0000x reference)
#include <cuda_runtime.h>
#include <cuda_fp16.h>
#include <math.h>
#include <stdint.h>

// ---------------- problem constants ----------------
#define NB      16384
#define FEAT    2048
#define NCOL    2048
#define KH      2112            // 64 (S cols) + 2048 (V cols)
#define MTILE   128
#define RBLKS   (NB/MTILE)      // 128
#define NBLK    16
#define NPAIR   136             // triangular block pairs
#define THREADS 256
// shared tile geometry (KT=64, verified R10/R14 main = 417us)
#define KTM     64
#define ROWB_M  144             // 128B data + 16B pad (ldsm conflict-free)
#define MATB_M  (MTILE*ROWB_M)  // 18432
// main: 3 matrices (xq, Hh, Hl)
#define STAGE_M (3*MATB_M)      // 55296
#define SMEM_M  (2*STAGE_M)     // 110592 -> 2 CTAs/SM
// H-build: 2 matrices (A chunk, B chunk)
#define STAGE_H (2*MATB_M)      // 36864
#define SMEM_HV (2*STAGE_H)     // 73728 -> 2 CTAs/SM
#define VS_SCALE 64.0f
#define NHV     1224            // 136 pairs * 9 chunks
#define KSUB    704             // 11 stages of 64
#define NSTH    11

// ---------------- device scratch (alloc-free rule) ----------------
__device__ __half g_xq[(size_t)NB*FEAT];
__device__ __half g_ah[(size_t)FEAT*KH];
__device__ __half g_al[(size_t)FEAT*KH];
__device__ __half g_bh[(size_t)FEAT*KH];
__device__ __half g_bl[(size_t)FEAT*KH];
__device__ float  g_Hp9[(size_t)9*NPAIR*16384];     // per-(chunk,pair) 128x128 tiles
__device__ __half g_Hh[(size_t)FEAT*FEAT];          // scaled-H split hi [f'][f]
__device__ __half g_Hl[(size_t)FEAT*FEAT];
__device__ float  g_lin[NB];
__device__ float  g_zpart[NBLK][NB];

// ---------------- PTX helpers ----------------
__device__ __forceinline__ uint32_t smem_u32(const void* p) {
    uint32_t a;
    asm("{ .reg .u64 t; cvta.to.shared.u64 t, %1; cvt.u32.u64 %0, t; }" : "=r"(a) : "l"(p));
    return a;
}
__device__ __forceinline__ void cp16(uint32_t saddr, const void* gptr) {
    asm volatile("cp.async.cg.shared.global [%0], [%1], 16;" :: "r"(saddr), "l"(gptr) : "memory");
}
__device__ __forceinline__ void cpcommit() {
    asm volatile("cp.async.commit_group;" ::: "memory");
}
template<int N> __device__ __forceinline__ void cpwait() {
    asm volatile("cp.async.wait_group %0;" :: "n"(N) : "memory");
}
__device__ __forceinline__ void ldsm4(uint32_t* r, uint32_t addr) {
    asm volatile("ldmatrix.sync.aligned.m8n8.x4.shared.b16 {%0,%1,%2,%3}, [%4];"
                 : "=r"(r[0]), "=r"(r[1]), "=r"(r[2]), "=r"(r[3]) : "r"(addr));
}
__device__ __forceinline__ void mma_f16(float* d, const uint32_t* a,
                                        uint32_t b0, uint32_t b1) {
    asm volatile(
        "mma.sync.aligned.m16n8k16.row.col.f32.f16.f16.f32 "
        "{%0,%1,%2,%3}, {%4,%5,%6,%7}, {%8,%9}, {%0,%1,%2,%3};"
        : "+f"(d[0]), "+f"(d[1]), "+f"(d[2]), "+f"(d[3])
        : "r"(a[0]), "r"(a[1]), "r"(a[2]), "r"(a[3]), "r"(b0), "r"(b1));
}
__device__ __forceinline__ void f16split(float v, __half& h, __half& l) {
    h = __float2half(v);
    l = __float2half(v - __half2float(h));
}

// ================= prep_v: V-split + S-build (DRAM-bound) =================
__global__ void __launch_bounds__(256)
prep_v(const float* __restrict__ v) {
    const int t = threadIdx.x;
    if (blockIdx.x < FEAT) {
        const int f = blockIdx.x;
        const size_t vb = (size_t)f * NCOL;
        const size_t ob = (size_t)f * KH + 64;
#pragma unroll
        for (int i = 0; i < NCOL / 256; ++i) {
            const int n = t + i * 256;
            const float val = v[vb + n] * VS_SCALE;
            __half h, l;
            f16split(val, h, l);
            g_bh[ob + n] = h;
            g_bl[ob + n] = l;
            g_ah[ob + n] = __hneg(h);
            g_al[ob + n] = __hneg(l);
        }
    } else {
        __shared__ float rowbuf[NCOL];
        const int f = blockIdx.x - FEAT;
        for (int i = t; i < NCOL; i += 256)
            rowbuf[i] = v[(size_t)f * NCOL + i];
        __syncthreads();
        if (t < 64) {
            float val = 0.f;
#pragma unroll
            for (int s = 0; s < 32; ++s) val += rowbuf[s * 64 + t];
            val *= VS_SCALE;
            __half h, l;
            f16split(val, h, l);
            const size_t o = (size_t)f * KH + t;
            g_ah[o] = h;
            g_al[o] = l;
            g_bh[o] = h;
            g_bl[o] = l;
        }
    }
}

// ================= merged: virtual-K H-build chunks + x prep =================
// bid < NHV: chunk cz = bid/136 (prod = cz/3, ksub = cz%3), pair p = bid%136.
//   H slice = A_prod[I-rows] * B_prod[J-rows]^T over K [ksub*704, +704).
//   Inner loop is main's measured-best shape (KT=64, 32x64 warp tile).
// bid >= NHV: x quantize + linear dot (one row per CTA).
__global__ void __launch_bounds__(THREADS, 2)
prep_Hvx(const float* __restrict__ x, const float* __restrict__ w) {
    extern __shared__ char smem[];
    const int tid = threadIdx.x;

    if (blockIdx.x < NHV) {
        const uint32_t sb = smem_u32(smem);
        const int lane = tid & 31;
        const int wid  = tid >> 5;
        const int wm   = wid >> 1;        // 0..3 (M32 each, I-side)
        const int wn   = wid & 1;         // 0..1 (N64 each, J-side)
        const int lrow = lane & 15;
        const int lkb  = (lane >> 4) * 16;

        const int cz   = blockIdx.x / NPAIR;   // 0..8
        const int prod = cz / 3;               // 0: Ah*Bh, 1: Ah*Bl, 2: Al*Bh
        const int k0   = (cz % 3) * KSUB;
        int t = blockIdx.x % NPAIR;
        int J = 0;
        while (t > J) { t -= (J + 1); ++J; }
        const int I = t;

        const __half* pA = (prod == 2) ? g_al : g_ah;
        const __half* pB = (prod == 1) ? g_bl : g_bh;
        const __half* gA = pA + (size_t)(I * 128) * KH + k0;
        const __half* gB = pB + (size_t)(J * 128) * KH + k0;

        float acc[2][8][4];
#pragma unroll
        for (int i = 0; i < 2; ++i)
#pragma unroll
            for (int j = 0; j < 8; ++j)
#pragma unroll
                for (int c = 0; c < 4; ++c) acc[i][j][c] = 0.f;

        // 8 cp16/thread: ids 0..1023 A (128 rows x 8 q), 1024..2047 B
        auto load_stage = [&](int st) {
            const uint32_t dst = sb + (uint32_t)(st & 1) * STAGE_H;
            const uint32_t kk0 = (uint32_t)st * KTM;
#pragma unroll
            for (int i = 0; i < 8; ++i) {
                const int id  = tid + i * 256;
                const int mat = id >> 10;
                const int row = (id >> 3) & 127;
                const int q   = id & 7;
                const __half* g = mat ? gB : gA;
                cp16(dst + (uint32_t)(mat * MATB_M + row * ROWB_M + q * 16),
                     g + (size_t)row * KH + kk0 + q * 8);
            }
            cpcommit();
        };

        load_stage(0);
        for (int s = 0; s < NSTH; ++s) {
            if (s + 1 < NSTH) { load_stage(s + 1); cpwait<1>(); }
            else              { cpwait<0>(); }
            __syncthreads();

            const uint32_t base = sb + (uint32_t)(s & 1) * STAGE_H;
#pragma unroll
            for (int kk = 0; kk < 4; ++kk) {
                uint32_t ax[2][4];
#pragma unroll
                for (int i = 0; i < 2; ++i)
                    ldsm4(ax[i], base + (uint32_t)((wm * 32 + i * 16 + lrow) * ROWB_M
                                                   + kk * 32 + lkb));
#pragma unroll
                for (int g = 0; g < 4; ++g) {
                    uint32_t bb[4];
                    ldsm4(bb, base + MATB_M
                          + (uint32_t)((wn * 64 + g * 16 + lrow) * ROWB_M
                                       + kk * 32 + lkb));
#pragma unroll
                    for (int i = 0; i < 2; ++i) {
                        mma_f16(acc[i][2 * g],     ax[i], bb[0], bb[2]);
                        mma_f16(acc[i][2 * g + 1], ax[i], bb[1], bb[3]);
                    }
                }
            }
            __syncthreads();
        }

        // epilogue: transpose via smem (128x129 floats = 66048 <= 73728),
        // store compact tile [B-row][A-row], coalesced.
        float* sbuf = (float*)smem;
#pragma unroll
        for (int i = 0; i < 2; ++i)
#pragma unroll
            for (int j = 0; j < 8; ++j)
#pragma unroll
                for (int c = 0; c < 4; ++c) {
                    const int r  = wm * 32 + i * 16 + (lane >> 2) + (c >> 1) * 8;   // A-row
                    const int cc = wn * 64 + j * 8 + (lane & 3) * 2 + (c & 1);      // B-row
                    sbuf[r * 129 + cc] = acc[i][j][c];
                }
        __syncthreads();

        const int c   = tid >> 1;               // B-row
        const int seg = (tid & 1) * 64;         // A-row segment
        float* dst = &g_Hp9[((size_t)cz * NPAIR + (size_t)(blockIdx.x % NPAIR)) * 16384
                            + c * 128 + seg];
#pragma unroll
        for (int i = 0; i < 64; ++i)
            dst[i] = sbuf[(seg + i) * 129 + c];
    } else {
        // ---- x quantize + linear dot ----
        const int row = blockIdx.x - NHV;
        const size_t base = (size_t)row * FEAT;
        float dot = 0.f;
#pragma unroll
        for (int i = 0; i < FEAT / 256; ++i) {
            int k = tid + i * 256;
            float xv = x[base + k];
            g_xq[base + k] = __float2half(xv);
            dot = fmaf(xv, w[k], dot);
        }
#pragma unroll
        for (int m = 16; m > 0; m >>= 1) dot += __shfl_xor_sync(0xffffffffu, dot, m);
        float* part = (float*)smem;
        if ((tid & 31) == 0) part[tid >> 5] = dot;
        __syncthreads();
        if (tid == 0) {
            float s = 0.f;
#pragma unroll
            for (int i = 0; i < 8; ++i) s += part[i];
            g_lin[row] = s;
        }
    }
}

// ================= conv_H9: sum 9 slices, scale, split to fp16 =================
// grid 136*8; each CTA: 2048 elems of pair p. tile elem e = crow*128 + a
// -> H row J*128+crow, col I*128+a.
__global__ void __launch_bounds__(256)
conv_H9() {
    const int p   = blockIdx.x >> 3;
    const int sub = blockIdx.x & 7;
    const int t   = threadIdx.x;
    int tt = p;
    int J = 0;
    while (tt > J) { tt -= (J + 1); ++J; }
    const int I = tt;
    const float scale = (I == J) ? 0.25f : 0.5f;

    const size_t tbase = (size_t)p * 16384 + sub * 2048 + t * 8;
#pragma unroll
    for (int hq = 0; hq < 2; ++hq) {
        const size_t e = tbase + hq * 4;
        float4 s = make_float4(0.f, 0.f, 0.f, 0.f);
#pragma unroll
        for (int c = 0; c < 9; ++c) {
            const float4 v = *(const float4*)&g_Hp9[(size_t)c * NPAIR * 16384 + e];
            s.x += v.x; s.y += v.y; s.z += v.z; s.w += v.w;
        }
        const int le   = (int)(e & 16383);
        const int crow = le >> 7;
        const int a    = le & 127;
        const size_t o = (size_t)(J * 128 + crow) * FEAT + I * 128 + a;
        float vals[4] = {s.x * scale, s.y * scale, s.z * scale, s.w * scale};
#pragma unroll
        for (int i = 0; i < 4; ++i) {
            __half h, l;
            f16split(vals[i], h, l);
            g_Hh[o + i] = h;
            g_Hl[o + i] = l;
        }
    }
}

// ================= main: verbatim R10/R14 (measured 417us) =================
__global__ void __launch_bounds__(THREADS, 2)
ffm_main(const float* __restrict__ x) {
    extern __shared__ char smem[];
    const uint32_t sb = smem_u32(smem);
    const int tid  = threadIdx.x;
    const int lane = tid & 31;
    const int wid  = tid >> 5;
    const int wm   = wid >> 1;        // 0..3 (M32 each)
    const int wn   = wid & 1;         // 0..1 (N64 each)
    const int grp  = blockIdx.x >> 7;
    const int rb   = blockIdx.x & 127;
    const int rblk = rb * MTILE;
    const int J    = (NBLK - 1) - grp;    // longest first
    const int nst  = (J + 1) * 2;         // KT=64
    const int lrow = lane & 15;
    const int lkb  = (lane >> 4) * 16;

    float acc[2][8][4];
#pragma unroll
    for (int i = 0; i < 2; ++i)
#pragma unroll
        for (int j = 0; j < 8; ++j)
#pragma unroll
            for (int c = 0; c < 4; ++c) acc[i][j][c] = 0.f;

    uint32_t cp_so[12];
    uint32_t cp_go[12];
#pragma unroll
    for (int i = 0; i < 12; ++i) {
        const int id  = tid + i * 256;
        const int mat = id >> 10;
        const int row = (id >> 3) & 127;
        const int q   = id & 7;
        cp_so[i] = (uint32_t)(mat * MATB_M + row * ROWB_M + q * 16);
        cp_go[i] = (uint32_t)(row * FEAT + q * 8);
    }
    const __half* gx = g_xq + (size_t)rblk * FEAT;
    const __half* gh = g_Hh + (size_t)J * 128 * FEAT;
    const __half* gl = g_Hl + (size_t)J * 128 * FEAT;

    auto load_stage = [&](int st) {
        const uint32_t dst = sb + (uint32_t)(st & 1) * STAGE_M;
        const uint32_t k0 = (uint32_t)st * KTM;
#pragma unroll
        for (int i = 0; i < 12; ++i) {
            const int mat = (tid + i * 256) >> 10;
            const __half* g = (mat == 0) ? gx : (mat == 1) ? gh : gl;
            cp16(dst + cp_so[i], g + cp_go[i] + k0);
        }
        cpcommit();
    };

    load_stage(0);
    for (int s = 0; s < nst; ++s) {
        if (s + 1 < nst) { load_stage(s + 1); cpwait<1>(); }
        else             { cpwait<0>(); }
        __syncthreads();

        const uint32_t base = sb + (uint32_t)(s & 1) * STAGE_M;
#pragma unroll
        for (int kk = 0; kk < 4; ++kk) {
            uint32_t ax[2][4];
#pragma unroll
            for (int i = 0; i < 2; ++i)
                ldsm4(ax[i], base + (uint32_t)((wm * 32 + i * 16 + lrow) * ROWB_M
                                               + kk * 32 + lkb));
#pragma unroll
            for (int g = 0; g < 4; ++g) {
                const uint32_t bo = base + MATB_M
                    + (uint32_t)((wn * 64 + g * 16 + lrow) * ROWB_M + kk * 32 + lkb);
                uint32_t hh[4], hl[4];
                ldsm4(hh, bo);
                ldsm4(hl, bo + MATB_M);
#pragma unroll
                for (int i = 0; i < 2; ++i) {
                    float* d0 = acc[i][2 * g];
                    float* d1 = acc[i][2 * g + 1];
                    mma_f16(d0, ax[i], hh[0], hh[2]);
                    mma_f16(d0, ax[i], hl[0], hl[2]);
                    mma_f16(d1, ax[i], hh[1], hh[3]);
                    mma_f16(d1, ax[i], hl[1], hl[3]);
                }
            }
        }
        __syncthreads();
    }

    // ---- epilogue: part = dot(acc_row, x_row[J-block]) ----
    float* zbuf = (float*)smem;
    if (tid < MTILE) zbuf[tid] = 0.f;
    __syncthreads();

    float part[2][2] = {{0.f, 0.f}, {0.f, 0.f}};
#pragma unroll
    for (int i = 0; i < 2; ++i)
#pragma unroll
        for (int h = 0; h < 2; ++h) {
            const int row = rblk + wm * 32 + i * 16 + (lane >> 2) + h * 8;
            const float* xr = x + (size_t)row * FEAT + J * 128 + wn * 64
                              + (lane & 3) * 2;
#pragma unroll
            for (int j = 0; j < 8; ++j) {
                const float2 xv = *(const float2*)(xr + j * 8);
                part[i][h] += acc[i][j][2 * h] * xv.x + acc[i][j][2 * h + 1] * xv.y;
            }
        }

#pragma unroll
    for (int m = 1; m < 4; m <<= 1)
#pragma unroll
        for (int i = 0; i < 2; ++i)
#pragma unroll
            for (int h = 0; h < 2; ++h)
                part[i][h] += __shfl_xor_sync(0xffffffffu, part[i][h], m);
    if ((lane & 3) == 0) {
#pragma unroll
        for (int i = 0; i < 2; ++i)
#pragma unroll
            for (int h = 0; h < 2; ++h)
                atomicAdd(&zbuf[wm * 32 + i * 16 + (lane >> 2) + h * 8], part[i][h]);
    }
    __syncthreads();
    if (tid < MTILE)
        g_zpart[grp][rblk + tid] = zbuf[tid];
}

// ================= final combine =================
__global__ void __launch_bounds__(256)
ffm_fin(const float* __restrict__ bias, float* __restrict__ out) {
    const int row = blockIdx.x * 256 + threadIdx.x;
    float zs = 0.f;
#pragma unroll
    for (int u = 0; u < NBLK; ++u) zs += g_zpart[u][row];
    const float z = 4.8828125e-4f * zs + g_lin[row] + bias[0];  // 0.5 * 2^-10
    out[row] = 1.f / (1.f + expf(-z));
}

// ================= launch =================
extern "C" void kernel_launch(void* const* d_in, const int* in_sizes, int n_in,
                              void* d_out, int out_size) {
    const float* x = (const float*)d_in[0];
    const float* w = (const float*)d_in[1];
    const float* b = (const float*)d_in[2];
    const float* v = (const float*)d_in[3];
    float* out = (float*)d_out;

    cudaFuncSetAttribute(prep_Hvx, cudaFuncAttributeMaxDynamicSharedMemorySize, SMEM_HV);
    cudaFuncSetAttribute(ffm_main, cudaFuncAttributeMaxDynamicSharedMemorySize, SMEM_M);

    prep_v<<<2 * FEAT, 256>>>(v);
    prep_Hvx<<<NHV + NB, THREADS, SMEM_HV>>>(x, w);
    conv_H9<<<NPAIR * 8, 256>>>();
    ffm_main<<<NBLK * RBLKS, THREADS, SMEM_M>>>(x);
    ffm_fin<<<NB / 256, 256>>>(b, out);
}

// round 16
// speedup vs baseline: 1.1877x; 1.1877x over previous
#include <cuda_runtime.h>
#include <cuda_fp16.h>
#include <math.h>
#include <stdint.h>

// ---------------- problem constants ----------------
#define NB      16384
#define FEAT    2048
#define NCOL    2048
#define KH      2112            // 64 (S cols) + 2048 (V cols)
#define MTILE   128
#define RBLKS   (NB/MTILE)      // 128
#define NBLK    16
#define THREADS 256
// prep_H tiles (KT=32, verified R3-R14)
#define ROWB    80
#define MATB    (MTILE*ROWB)    // 10240
#define STAGE4  (4*MATB)
#define SMEM_H  (2*STAGE4)      // 81920
// main tiles (KT=64, verified R10/R14 = 417us)
#define KTM     64
#define ROWB_M  144             // 128B data + 16B pad (ldsm conflict-free)
#define MATB_M  (MTILE*ROWB_M)  // 18432
#define STAGE_M (3*MATB_M)      // 55296
#define SMEM_M  (2*STAGE_M)     // 110592 -> 2 CTAs/SM
#define VS_SCALE 64.0f
#define NHB     272

// ---------------- device scratch (alloc-free rule) ----------------
__device__ __half g_xq[(size_t)NB*FEAT];
__device__ __half g_ah[(size_t)FEAT*KH];
__device__ __half g_al[(size_t)FEAT*KH];
__device__ __half g_bh[(size_t)FEAT*KH];
__device__ __half g_bl[(size_t)FEAT*KH];
__device__ float  g_Hp[2][(size_t)FEAT*FEAT];
__device__ __half g_Hh[(size_t)FEAT*FEAT];
__device__ __half g_Hl[(size_t)FEAT*FEAT];
__device__ float  g_lin[NB];
__device__ float  g_zpart[NBLK][NB];

// ---------------- PTX helpers ----------------
__device__ __forceinline__ uint32_t smem_u32(const void* p) {
    uint32_t a;
    asm("{ .reg .u64 t; cvta.to.shared.u64 t, %1; cvt.u32.u64 %0, t; }" : "=r"(a) : "l"(p));
    return a;
}
__device__ __forceinline__ void cp16(uint32_t saddr, const void* gptr) {
    asm volatile("cp.async.cg.shared.global [%0], [%1], 16;" :: "r"(saddr), "l"(gptr) : "memory");
}
__device__ __forceinline__ void cpcommit() {
    asm volatile("cp.async.commit_group;" ::: "memory");
}
template<int N> __device__ __forceinline__ void cpwait() {
    asm volatile("cp.async.wait_group %0;" :: "n"(N) : "memory");
}
__device__ __forceinline__ void ldsm4(uint32_t* r, uint32_t addr) {
    asm volatile("ldmatrix.sync.aligned.m8n8.x4.shared.b16 {%0,%1,%2,%3}, [%4];"
                 : "=r"(r[0]), "=r"(r[1]), "=r"(r[2]), "=r"(r[3]) : "r"(addr));
}
__device__ __forceinline__ void mma_f16(float* d, const uint32_t* a,
                                        uint32_t b0, uint32_t b1) {
    asm volatile(
        "mma.sync.aligned.m16n8k16.row.col.f32.f16.f16.f32 "
        "{%0,%1,%2,%3}, {%4,%5,%6,%7}, {%8,%9}, {%0,%1,%2,%3};"
        : "+f"(d[0]), "+f"(d[1]), "+f"(d[2]), "+f"(d[3])
        : "r"(a[0]), "r"(a[1]), "r"(a[2]), "r"(a[3]), "r"(b0), "r"(b1));
}
__device__ __forceinline__ void f16split(float v, __half& h, __half& l) {
    h = __float2half(v);
    l = __float2half(v - __half2float(h));
}

// ================= prep_all: ALL DRAM-bound prep in one launch =================
// bid < FEAT:  V part of A'/B' (cols 64..2111, scaled, A' negated) + fused S
//              (cols 0..63) — each thread's n-slots all map to k = t&63, so the
//              field-sum is a 256->64 smem reduce, no second v read.
// bid >= FEAT: x quantize + linear dot (one row per CTA).
__global__ void __launch_bounds__(256)
prep_all(const float* __restrict__ v, const float* __restrict__ x,
         const float* __restrict__ w) {
    const int t = threadIdx.x;
    if (blockIdx.x < FEAT) {
        __shared__ float psm[256];
        const int f = blockIdx.x;
        const size_t vb = (size_t)f * NCOL;
        const size_t ob = (size_t)f * KH + 64;
        float partial = 0.f;
#pragma unroll
        for (int i = 0; i < NCOL / 256; ++i) {
            const int n = t + i * 256;
            const float val = v[vb + n] * VS_SCALE;
            partial += val;                       // k-slot = n&63 = t&63
            __half h, l;
            f16split(val, h, l);
            g_bh[ob + n] = h;
            g_bl[ob + n] = l;
            g_ah[ob + n] = __hneg(h);
            g_al[ob + n] = __hneg(l);
        }
        psm[t] = partial;
        __syncthreads();
        if (t < 64) {
            const float s = psm[t] + psm[t + 64] + psm[t + 128] + psm[t + 192];
            __half h, l;
            f16split(s, h, l);
            const size_t o = (size_t)f * KH + t;
            g_ah[o] = h;
            g_al[o] = l;
            g_bh[o] = h;
            g_bl[o] = l;
        }
    } else {
        const int row = blockIdx.x - FEAT;
        const size_t base = (size_t)row * FEAT;
        float dot = 0.f;
#pragma unroll
        for (int i = 0; i < FEAT / 256; ++i) {
            int k = t + i * 256;
            float xv = x[base + k];
            g_xq[base + k] = __float2half(xv);
            dot = fmaf(xv, w[k], dot);
        }
#pragma unroll
        for (int m = 16; m > 0; m >>= 1) dot += __shfl_xor_sync(0xffffffffu, dot, m);
        __shared__ float part[8];
        if ((t & 31) == 0) part[t >> 5] = dot;
        __syncthreads();
        if (t == 0) {
            float s = 0.f;
#pragma unroll
            for (int i = 0; i < 8; ++i) s += part[i];
            g_lin[row] = s;
        }
    }
}

// ---- 4-matrix 3-product mainloop for H build (verified, KT=32) ----
__device__ __forceinline__ void gemm_tile4(
    uint32_t sb, float acc[2][8][4],
    const __half* pAh, const __half* pAl, int arow0,
    const __half* pBh, const __half* pBl, int brow0,
    size_t stride, int kbase, int nst)
{
    const int tid  = threadIdx.x;
    const int lane = tid & 31;
    const int wid  = tid >> 5;
    const int wm   = wid >> 1;
    const int wn   = wid & 1;
    const int lrow = lane & 15;
    const int lkb  = (lane >> 4) * 16;

    auto load_stage = [&](int st) {
        const uint32_t dst = sb + (uint32_t)(st & 1) * STAGE4;
        const int k0 = kbase + st * 32;
#pragma unroll
        for (int i = 0; i < 8; ++i) {
            const int id  = tid + i * 256;
            const int mat = id >> 9;
            const int row = (id >> 2) & 127;
            const int q   = id & 3;
            const uint32_t so = dst + mat * MATB + (uint32_t)(row * ROWB + q * 16);
            const __half* g =
                (mat == 0) ? pAh : (mat == 1) ? pAl : (mat == 2) ? pBh : pBl;
            const size_t go = (mat < 2)
                ? ((size_t)(arow0 + row) * stride + k0 + q * 8)
                : ((size_t)(brow0 + row) * stride + k0 + q * 8);
            cp16(so, g + go);
        }
        cpcommit();
    };

    load_stage(0);
    for (int s = 0; s < nst; ++s) {
        if (s + 1 < nst) { load_stage(s + 1); cpwait<1>(); }
        else             { cpwait<0>(); }
        __syncthreads();

        const uint32_t base = sb + (uint32_t)(s & 1) * STAGE4;
#pragma unroll
        for (int kk = 0; kk < 2; ++kk) {
            uint32_t ah[2][4], al[2][4];
#pragma unroll
            for (int i = 0; i < 2; ++i) {
                const uint32_t ao = base + (uint32_t)((wm * 32 + i * 16 + lrow) * ROWB
                                                      + kk * 32 + lkb);
                ldsm4(ah[i], ao);
                ldsm4(al[i], ao + MATB);
            }
#pragma unroll
            for (int g = 0; g < 4; ++g) {
                const uint32_t bo = base + 2 * MATB
                    + (uint32_t)((wn * 64 + g * 16 + lrow) * ROWB + kk * 32 + lkb);
                uint32_t bh[4], bl[4];
                ldsm4(bh, bo);
                ldsm4(bl, bo + MATB);
#pragma unroll
                for (int i = 0; i < 2; ++i) {
                    float* d0 = acc[i][2 * g];
                    float* d1 = acc[i][2 * g + 1];
                    mma_f16(d0, ah[i], bh[0], bh[2]);
                    mma_f16(d0, ah[i], bl[0], bl[2]);
                    mma_f16(d0, al[i], bh[0], bh[2]);
                    mma_f16(d1, ah[i], bh[1], bh[3]);
                    mma_f16(d1, ah[i], bl[1], bl[3]);
                    mma_f16(d1, al[i], bh[1], bh[3]);
                }
            }
        }
        __syncthreads();
    }
}

// ================= H builder: 272 CTAs, tensor-bound, runs alone =================
__global__ void __launch_bounds__(256, 2)
prep_H() {
    extern __shared__ char smem[];
    const uint32_t sb = smem_u32(smem);
    const int tid  = threadIdx.x;
    const int lane = tid & 31;
    const int wid  = tid >> 5;
    const int wm   = wid >> 1;
    const int wn   = wid & 1;
    const int half = blockIdx.x & 1;
    int t = blockIdx.x >> 1;
    int J = 0;
    while (t > J) { t -= (J + 1); ++J; }
    const int I = t;

    float acc[2][8][4];
#pragma unroll
    for (int i = 0; i < 2; ++i)
#pragma unroll
        for (int j = 0; j < 8; ++j)
#pragma unroll
            for (int c = 0; c < 4; ++c) acc[i][j][c] = 0.f;

    gemm_tile4(sb, acc, g_ah, g_al, I * 128, g_bh, g_bl, J * 128,
               KH, half * 1056, 33);

    float* sbuf = (float*)smem;    // 128*129*4 = 66048 <= 81920
#pragma unroll
    for (int i = 0; i < 2; ++i)
#pragma unroll
        for (int j = 0; j < 8; ++j)
#pragma unroll
            for (int c = 0; c < 4; ++c) {
                const int r  = wm * 32 + i * 16 + (lane >> 2) + (c >> 1) * 8;
                const int cc = wn * 64 + j * 8 + (lane & 3) * 2 + (c & 1);
                sbuf[r * 129 + cc] = acc[i][j][c];
            }
    __syncthreads();

    const int c   = tid >> 1;
    const int seg = (tid & 1) * 64;
    float* dst = &g_Hp[half][(size_t)(J * 128 + c) * FEAT + I * 128 + seg];
#pragma unroll
    for (int i = 0; i < 64; ++i)
        dst[i] = sbuf[(seg + i) * 129 + c];
}

// combine chunks; net scale = 1024/VS_SCALE^2 = 1/4, x2 on off-diagonal blocks
__global__ void __launch_bounds__(256) conv_H() {
    const int fp = blockIdx.x;
    const int t  = threadIdx.x;
    const size_t rb = (size_t)fp * FEAT;
#pragma unroll
    for (int i = 0; i < FEAT / 256; ++i) {
        const int f = t + i * 256;
        float p = g_Hp[0][rb + f] + g_Hp[1][rb + f];
        p *= ((f >> 7) != (fp >> 7)) ? 0.5f : 0.25f;
        __half h, l;
        f16split(p, h, l);
        g_Hh[rb + f] = h;
        g_Hl[rb + f] = l;
    }
}

// ================= main: verbatim R10/R14 (measured 417us) =================
// grid 2048: grp = bid>>7 -> J = 15-grp (LPT); rb = bid&127; nst = (J+1)*2.
// 8 warps = 4wm x 2wn, warp tile 32x64, KT=64, 2 CTAs/SM.
__global__ void __launch_bounds__(THREADS, 2)
ffm_main(const float* __restrict__ x) {
    extern __shared__ char smem[];
    const uint32_t sb = smem_u32(smem);
    const int tid  = threadIdx.x;
    const int lane = tid & 31;
    const int wid  = tid >> 5;
    const int wm   = wid >> 1;        // 0..3 (M32 each)
    const int wn   = wid & 1;         // 0..1 (N64 each)
    const int grp  = blockIdx.x >> 7;
    const int rb   = blockIdx.x & 127;
    const int rblk = rb * MTILE;
    const int J    = (NBLK - 1) - grp;    // longest first
    const int nst  = (J + 1) * 2;         // KT=64
    const int lrow = lane & 15;
    const int lkb  = (lane >> 4) * 16;

    float acc[2][8][4];
#pragma unroll
    for (int i = 0; i < 2; ++i)
#pragma unroll
        for (int j = 0; j < 8; ++j)
#pragma unroll
            for (int c = 0; c < 4; ++c) acc[i][j][c] = 0.f;

    uint32_t cp_so[12];
    uint32_t cp_go[12];
#pragma unroll
    for (int i = 0; i < 12; ++i) {
        const int id  = tid + i * 256;
        const int mat = id >> 10;
        const int row = (id >> 3) & 127;
        const int q   = id & 7;
        cp_so[i] = (uint32_t)(mat * MATB_M + row * ROWB_M + q * 16);
        cp_go[i] = (uint32_t)(row * FEAT + q * 8);
    }
    const __half* gx = g_xq + (size_t)rblk * FEAT;
    const __half* gh = g_Hh + (size_t)J * 128 * FEAT;
    const __half* gl = g_Hl + (size_t)J * 128 * FEAT;

    auto load_stage = [&](int st) {
        const uint32_t dst = sb + (uint32_t)(st & 1) * STAGE_M;
        const uint32_t k0 = (uint32_t)st * KTM;
#pragma unroll
        for (int i = 0; i < 12; ++i) {
            const int mat = (tid + i * 256) >> 10;
            const __half* g = (mat == 0) ? gx : (mat == 1) ? gh : gl;
            cp16(dst + cp_so[i], g + cp_go[i] + k0);
        }
        cpcommit();
    };

    load_stage(0);
    for (int s = 0; s < nst; ++s) {
        if (s + 1 < nst) { load_stage(s + 1); cpwait<1>(); }
        else             { cpwait<0>(); }
        __syncthreads();

        const uint32_t base = sb + (uint32_t)(s & 1) * STAGE_M;
#pragma unroll
        for (int kk = 0; kk < 4; ++kk) {
            uint32_t ax[2][4];
#pragma unroll
            for (int i = 0; i < 2; ++i)
                ldsm4(ax[i], base + (uint32_t)((wm * 32 + i * 16 + lrow) * ROWB_M
                                               + kk * 32 + lkb));
#pragma unroll
            for (int g = 0; g < 4; ++g) {
                const uint32_t bo = base + MATB_M
                    + (uint32_t)((wn * 64 + g * 16 + lrow) * ROWB_M + kk * 32 + lkb);
                uint32_t hh[4], hl[4];
                ldsm4(hh, bo);
                ldsm4(hl, bo + MATB_M);
#pragma unroll
                for (int i = 0; i < 2; ++i) {
                    float* d0 = acc[i][2 * g];
                    float* d1 = acc[i][2 * g + 1];
                    mma_f16(d0, ax[i], hh[0], hh[2]);
                    mma_f16(d0, ax[i], hl[0], hl[2]);
                    mma_f16(d1, ax[i], hh[1], hh[3]);
                    mma_f16(d1, ax[i], hl[1], hl[3]);
                }
            }
        }
        __syncthreads();
    }

    // ---- epilogue: part = dot(acc_row, x_row[J-block]) ----
    float* zbuf = (float*)smem;
    if (tid < MTILE) zbuf[tid] = 0.f;
    __syncthreads();

    float part[2][2] = {{0.f, 0.f}, {0.f, 0.f}};
#pragma unroll
    for (int i = 0; i < 2; ++i)
#pragma unroll
        for (int h = 0; h < 2; ++h) {
            const int row = rblk + wm * 32 + i * 16 + (lane >> 2) + h * 8;
            const float* xr = x + (size_t)row * FEAT + J * 128 + wn * 64
                              + (lane & 3) * 2;
#pragma unroll
            for (int j = 0; j < 8; ++j) {
                const float2 xv = *(const float2*)(xr + j * 8);
                part[i][h] += acc[i][j][2 * h] * xv.x + acc[i][j][2 * h + 1] * xv.y;
            }
        }

#pragma unroll
    for (int m = 1; m < 4; m <<= 1)
#pragma unroll
        for (int i = 0; i < 2; ++i)
#pragma unroll
            for (int h = 0; h < 2; ++h)
                part[i][h] += __shfl_xor_sync(0xffffffffu, part[i][h], m);
    if ((lane & 3) == 0) {
#pragma unroll
        for (int i = 0; i < 2; ++i)
#pragma unroll
            for (int h = 0; h < 2; ++h)
                atomicAdd(&zbuf[wm * 32 + i * 16 + (lane >> 2) + h * 8], part[i][h]);
    }
    __syncthreads();
    if (tid < MTILE)
        g_zpart[grp][rblk + tid] = zbuf[tid];
}

// ================= final combine =================
__global__ void __launch_bounds__(256)
ffm_fin(const float* __restrict__ bias, float* __restrict__ out) {
    const int row = blockIdx.x * 256 + threadIdx.x;
    float zs = 0.f;
#pragma unroll
    for (int u = 0; u < NBLK; ++u) zs += g_zpart[u][row];
    const float z = 4.8828125e-4f * zs + g_lin[row] + bias[0];  // 0.5 * 2^-10
    out[row] = 1.f / (1.f + expf(-z));
}

// ================= launch =================
extern "C" void kernel_launch(void* const* d_in, const int* in_sizes, int n_in,
                              void* d_out, int out_size) {
    const float* x = (const float*)d_in[0];
    const float* w = (const float*)d_in[1];
    const float* b = (const float*)d_in[2];
    const float* v = (const float*)d_in[3];
    float* out = (float*)d_out;

    cudaFuncSetAttribute(prep_H,   cudaFuncAttributeMaxDynamicSharedMemorySize, SMEM_H);
    cudaFuncSetAttribute(ffm_main, cudaFuncAttributeMaxDynamicSharedMemorySize, SMEM_M);

    prep_all<<<FEAT + NB, 256>>>(v, x, w);
    prep_H<<<NHB, 256, SMEM_H>>>();
    conv_H<<<FEAT, 256>>>();
    ffm_main<<<NBLK * RBLKS, THREADS, SMEM_M>>>(x);
    ffm_fin<<<NB / 256, 256>>>(b, out);
}

// round 17
// speedup vs baseline: 1.1960x; 1.0070x over previous
#include <cuda_runtime.h>
#include <cuda_fp16.h>
#include <math.h>
#include <stdint.h>

// ---------------- problem constants ----------------
#define NB      16384
#define FEAT    2048
#define NCOL    2048
#define KH      2112            // 64 (S cols) + 2048 (V cols)
#define MTILE   128
#define RBLKS   (NB/MTILE)      // 128
#define NBLK    16
#define THREADS 256
// prep_H tiles (KT=32, verified R3-R16)
#define ROWB    80
#define MATB    (MTILE*ROWB)    // 10240
#define STAGE4  (4*MATB)
#define SMEM_H  (2*STAGE4)      // 81920
// main tiles (KT=64, verified R10/R14/R16 = 418us)
#define KTM     64
#define ROWB_M  144             // 128B data + 16B pad (ldsm conflict-free)
#define MATB_M  (MTILE*ROWB_M)  // 18432
#define STAGE_M (3*MATB_M)      // 55296
#define SMEM_M  (2*STAGE_M)     // 110592 -> 2 CTAs/SM
#define VS_SCALE 64.0f
#define NHB     272

// ---------------- device scratch (alloc-free rule) ----------------
__device__ __half g_xq[(size_t)NB*FEAT];
__device__ __half g_ah[(size_t)FEAT*KH];
__device__ __half g_al[(size_t)FEAT*KH];
__device__ __half g_bh[(size_t)FEAT*KH];
__device__ __half g_bl[(size_t)FEAT*KH];
__device__ float  g_Hp[2][(size_t)FEAT*FEAT];
__device__ __half g_Hh[(size_t)FEAT*FEAT];
__device__ __half g_Hl[(size_t)FEAT*FEAT];
__device__ float  g_lin[NB];
__device__ float  g_zpart[NBLK][NB];

// ---------------- PTX helpers ----------------
__device__ __forceinline__ uint32_t smem_u32(const void* p) {
    uint32_t a;
    asm("{ .reg .u64 t; cvta.to.shared.u64 t, %1; cvt.u32.u64 %0, t; }" : "=r"(a) : "l"(p));
    return a;
}
__device__ __forceinline__ void cp16(uint32_t saddr, const void* gptr) {
    asm volatile("cp.async.cg.shared.global [%0], [%1], 16;" :: "r"(saddr), "l"(gptr) : "memory");
}
__device__ __forceinline__ void cpcommit() {
    asm volatile("cp.async.commit_group;" ::: "memory");
}
template<int N> __device__ __forceinline__ void cpwait() {
    asm volatile("cp.async.wait_group %0;" :: "n"(N) : "memory");
}
__device__ __forceinline__ void ldsm4(uint32_t* r, uint32_t addr) {
    asm volatile("ldmatrix.sync.aligned.m8n8.x4.shared.b16 {%0,%1,%2,%3}, [%4];"
                 : "=r"(r[0]), "=r"(r[1]), "=r"(r[2]), "=r"(r[3]) : "r"(addr));
}
__device__ __forceinline__ void mma_f16(float* d, const uint32_t* a,
                                        uint32_t b0, uint32_t b1) {
    asm volatile(
        "mma.sync.aligned.m16n8k16.row.col.f32.f16.f16.f32 "
        "{%0,%1,%2,%3}, {%4,%5,%6,%7}, {%8,%9}, {%0,%1,%2,%3};"
        : "+f"(d[0]), "+f"(d[1]), "+f"(d[2]), "+f"(d[3])
        : "r"(a[0]), "r"(a[1]), "r"(a[2]), "r"(a[3]), "r"(b0), "r"(b1));
}
__device__ __forceinline__ void f16split(float v, __half& h, __half& l) {
    h = __float2half(v);
    l = __float2half(v - __half2float(h));
}
__device__ __forceinline__ uint32_t h2u(__half2 h) {
    uint32_t u;
    __builtin_memcpy(&u, &h, 4);
    return u;
}

// ================= prep_all: ALL DRAM-bound prep, vectorized =================
// bid < FEAT:  V part of A'/B' (cols 64..2111, scaled, A' negated) + fused S
//              (cols 0..63). float4 loads, 8B (4xhalf) stores.
// bid >= FEAT: x quantize + linear dot (one row per CTA), float4/8B.
__global__ void __launch_bounds__(256)
prep_all(const float* __restrict__ v, const float* __restrict__ x,
         const float* __restrict__ w) {
    const int t = threadIdx.x;
    if (blockIdx.x < FEAT) {
        __shared__ float psm[4][256];
        const int f = blockIdx.x;
        const size_t vb = (size_t)f * NCOL;
        const size_t ob = (size_t)f * KH + 64;
        float ps0 = 0.f, ps1 = 0.f, ps2 = 0.f, ps3 = 0.f;
#pragma unroll
        for (int i = 0; i < 2; ++i) {
            const int n4 = (t + i * 256) * 4;     // stride 1024 == 0 mod 64
            float4 vv = *(const float4*)(v + vb + n4);
            vv.x *= VS_SCALE; vv.y *= VS_SCALE; vv.z *= VS_SCALE; vv.w *= VS_SCALE;
            ps0 += vv.x; ps1 += vv.y; ps2 += vv.z; ps3 += vv.w;
            __half h0, l0, h1, l1, h2, l2, h3, l3;
            f16split(vv.x, h0, l0);
            f16split(vv.y, h1, l1);
            f16split(vv.z, h2, l2);
            f16split(vv.w, h3, l3);
            const __half2 hh01 = __halves2half2(h0, h1);
            const __half2 hh23 = __halves2half2(h2, h3);
            const __half2 ll01 = __halves2half2(l0, l1);
            const __half2 ll23 = __halves2half2(l2, l3);
            *(uint2*)(g_bh + ob + n4) = make_uint2(h2u(hh01), h2u(hh23));
            *(uint2*)(g_bl + ob + n4) = make_uint2(h2u(ll01), h2u(ll23));
            *(uint2*)(g_ah + ob + n4) = make_uint2(h2u(__hneg2(hh01)), h2u(__hneg2(hh23)));
            *(uint2*)(g_al + ob + n4) = make_uint2(h2u(__hneg2(ll01)), h2u(__hneg2(ll23)));
        }
        psm[0][t] = ps0; psm[1][t] = ps1; psm[2][t] = ps2; psm[3][t] = ps3;
        __syncthreads();
        if (t < 64) {
            // slot t: contributed by threads t' = (t>>2) + 16m, component j = t&3
            const int j  = t & 3;
            const int tq = t >> 2;
            float s = 0.f;
#pragma unroll
            for (int m = 0; m < 16; ++m) s += psm[j][tq + 16 * m];
            __half h, l;
            f16split(s, h, l);
            const size_t o = (size_t)f * KH + t;
            g_ah[o] = h;
            g_al[o] = l;
            g_bh[o] = h;
            g_bl[o] = l;
        }
    } else {
        const int row = blockIdx.x - FEAT;
        const size_t base = (size_t)row * FEAT;
        float dot = 0.f;
#pragma unroll
        for (int i = 0; i < 2; ++i) {
            const int k4 = (t + i * 256) * 4;
            const float4 xv = *(const float4*)(x + base + k4);
            const float4 wv = *(const float4*)(w + k4);
            const __half2 h01 = __floats2half2_rn(xv.x, xv.y);
            const __half2 h23 = __floats2half2_rn(xv.z, xv.w);
            *(uint2*)(g_xq + base + k4) = make_uint2(h2u(h01), h2u(h23));
            dot = fmaf(xv.x, wv.x, dot);
            dot = fmaf(xv.y, wv.y, dot);
            dot = fmaf(xv.z, wv.z, dot);
            dot = fmaf(xv.w, wv.w, dot);
        }
#pragma unroll
        for (int m = 16; m > 0; m >>= 1) dot += __shfl_xor_sync(0xffffffffu, dot, m);
        __shared__ float part[8];
        if ((t & 31) == 0) part[t >> 5] = dot;
        __syncthreads();
        if (t == 0) {
            float s = 0.f;
#pragma unroll
            for (int i = 0; i < 8; ++i) s += part[i];
            g_lin[row] = s;
        }
    }
}

// ---- 4-matrix 3-product mainloop for H build (verified, KT=32) ----
__device__ __forceinline__ void gemm_tile4(
    uint32_t sb, float acc[2][8][4],
    const __half* pAh, const __half* pAl, int arow0,
    const __half* pBh, const __half* pBl, int brow0,
    size_t stride, int kbase, int nst)
{
    const int tid  = threadIdx.x;
    const int lane = tid & 31;
    const int wid  = tid >> 5;
    const int wm   = wid >> 1;
    const int wn   = wid & 1;
    const int lrow = lane & 15;
    const int lkb  = (lane >> 4) * 16;

    auto load_stage = [&](int st) {
        const uint32_t dst = sb + (uint32_t)(st & 1) * STAGE4;
        const int k0 = kbase + st * 32;
#pragma unroll
        for (int i = 0; i < 8; ++i) {
            const int id  = tid + i * 256;
            const int mat = id >> 9;
            const int row = (id >> 2) & 127;
            const int q   = id & 3;
            const uint32_t so = dst + mat * MATB + (uint32_t)(row * ROWB + q * 16);
            const __half* g =
                (mat == 0) ? pAh : (mat == 1) ? pAl : (mat == 2) ? pBh : pBl;
            const size_t go = (mat < 2)
                ? ((size_t)(arow0 + row) * stride + k0 + q * 8)
                : ((size_t)(brow0 + row) * stride + k0 + q * 8);
            cp16(so, g + go);
        }
        cpcommit();
    };

    load_stage(0);
    for (int s = 0; s < nst; ++s) {
        if (s + 1 < nst) { load_stage(s + 1); cpwait<1>(); }
        else             { cpwait<0>(); }
        __syncthreads();

        const uint32_t base = sb + (uint32_t)(s & 1) * STAGE4;
#pragma unroll
        for (int kk = 0; kk < 2; ++kk) {
            uint32_t ah[2][4], al[2][4];
#pragma unroll
            for (int i = 0; i < 2; ++i) {
                const uint32_t ao = base + (uint32_t)((wm * 32 + i * 16 + lrow) * ROWB
                                                      + kk * 32 + lkb);
                ldsm4(ah[i], ao);
                ldsm4(al[i], ao + MATB);
            }
#pragma unroll
            for (int g = 0; g < 4; ++g) {
                const uint32_t bo = base + 2 * MATB
                    + (uint32_t)((wn * 64 + g * 16 + lrow) * ROWB + kk * 32 + lkb);
                uint32_t bh[4], bl[4];
                ldsm4(bh, bo);
                ldsm4(bl, bo + MATB);
#pragma unroll
                for (int i = 0; i < 2; ++i) {
                    float* d0 = acc[i][2 * g];
                    float* d1 = acc[i][2 * g + 1];
                    mma_f16(d0, ah[i], bh[0], bh[2]);
                    mma_f16(d0, ah[i], bl[0], bl[2]);
                    mma_f16(d0, al[i], bh[0], bh[2]);
                    mma_f16(d1, ah[i], bh[1], bh[3]);
                    mma_f16(d1, ah[i], bl[1], bl[3]);
                    mma_f16(d1, al[i], bh[1], bh[3]);
                }
            }
        }
        __syncthreads();
    }
}

// ================= H builder: 272 CTAs, tensor-bound, runs alone =================
__global__ void __launch_bounds__(256, 2)
prep_H() {
    extern __shared__ char smem[];
    const uint32_t sb = smem_u32(smem);
    const int tid  = threadIdx.x;
    const int lane = tid & 31;
    const int wid  = tid >> 5;
    const int wm   = wid >> 1;
    const int wn   = wid & 1;
    const int half = blockIdx.x & 1;
    int t = blockIdx.x >> 1;
    int J = 0;
    while (t > J) { t -= (J + 1); ++J; }
    const int I = t;

    float acc[2][8][4];
#pragma unroll
    for (int i = 0; i < 2; ++i)
#pragma unroll
        for (int j = 0; j < 8; ++j)
#pragma unroll
            for (int c = 0; c < 4; ++c) acc[i][j][c] = 0.f;

    gemm_tile4(sb, acc, g_ah, g_al, I * 128, g_bh, g_bl, J * 128,
               KH, half * 1056, 33);

    float* sbuf = (float*)smem;    // 128*129*4 = 66048 <= 81920
#pragma unroll
    for (int i = 0; i < 2; ++i)
#pragma unroll
        for (int j = 0; j < 8; ++j)
#pragma unroll
            for (int c = 0; c < 4; ++c) {
                const int r  = wm * 32 + i * 16 + (lane >> 2) + (c >> 1) * 8;
                const int cc = wn * 64 + j * 8 + (lane & 3) * 2 + (c & 1);
                sbuf[r * 129 + cc] = acc[i][j][c];
            }
    __syncthreads();

    const int c   = tid >> 1;
    const int seg = (tid & 1) * 64;
    float* dst = &g_Hp[half][(size_t)(J * 128 + c) * FEAT + I * 128 + seg];
#pragma unroll
    for (int i = 0; i < 64; ++i)
        dst[i] = sbuf[(seg + i) * 129 + c];
}

// combine chunks; net scale = 1024/VS_SCALE^2 = 1/4, x2 on off-diagonal blocks
__global__ void __launch_bounds__(256) conv_H() {
    const int fp = blockIdx.x;
    const int t  = threadIdx.x;
    const size_t rb = (size_t)fp * FEAT;
#pragma unroll
    for (int i = 0; i < FEAT / 256; ++i) {
        const int f = t + i * 256;
        float p = g_Hp[0][rb + f] + g_Hp[1][rb + f];
        p *= ((f >> 7) != (fp >> 7)) ? 0.5f : 0.25f;
        __half h, l;
        f16split(p, h, l);
        g_Hh[rb + f] = h;
        g_Hl[rb + f] = l;
    }
}

// ================= main: verbatim R10/R14/R16 (measured 418us) =================
__global__ void __launch_bounds__(THREADS, 2)
ffm_main(const float* __restrict__ x) {
    extern __shared__ char smem[];
    const uint32_t sb = smem_u32(smem);
    const int tid  = threadIdx.x;
    const int lane = tid & 31;
    const int wid  = tid >> 5;
    const int wm   = wid >> 1;        // 0..3 (M32 each)
    const int wn   = wid & 1;         // 0..1 (N64 each)
    const int grp  = blockIdx.x >> 7;
    const int rb   = blockIdx.x & 127;
    const int rblk = rb * MTILE;
    const int J    = (NBLK - 1) - grp;    // longest first
    const int nst  = (J + 1) * 2;         // KT=64
    const int lrow = lane & 15;
    const int lkb  = (lane >> 4) * 16;

    float acc[2][8][4];
#pragma unroll
    for (int i = 0; i < 2; ++i)
#pragma unroll
        for (int j = 0; j < 8; ++j)
#pragma unroll
            for (int c = 0; c < 4; ++c) acc[i][j][c] = 0.f;

    uint32_t cp_so[12];
    uint32_t cp_go[12];
#pragma unroll
    for (int i = 0; i < 12; ++i) {
        const int id  = tid + i * 256;
        const int mat = id >> 10;
        const int row = (id >> 3) & 127;
        const int q   = id & 7;
        cp_so[i] = (uint32_t)(mat * MATB_M + row * ROWB_M + q * 16);
        cp_go[i] = (uint32_t)(row * FEAT + q * 8);
    }
    const __half* gx = g_xq + (size_t)rblk * FEAT;
    const __half* gh = g_Hh + (size_t)J * 128 * FEAT;
    const __half* gl = g_Hl + (size_t)J * 128 * FEAT;

    auto load_stage = [&](int st) {
        const uint32_t dst = sb + (uint32_t)(st & 1) * STAGE_M;
        const uint32_t k0 = (uint32_t)st * KTM;
#pragma unroll
        for (int i = 0; i < 12; ++i) {
            const int mat = (tid + i * 256) >> 10;
            const __half* g = (mat == 0) ? gx : (mat == 1) ? gh : gl;
            cp16(dst + cp_so[i], g + cp_go[i] + k0);
        }
        cpcommit();
    };

    load_stage(0);
    for (int s = 0; s < nst; ++s) {
        if (s + 1 < nst) { load_stage(s + 1); cpwait<1>(); }
        else             { cpwait<0>(); }
        __syncthreads();

        const uint32_t base = sb + (uint32_t)(s & 1) * STAGE_M;
#pragma unroll
        for (int kk = 0; kk < 4; ++kk) {
            uint32_t ax[2][4];
#pragma unroll
            for (int i = 0; i < 2; ++i)
                ldsm4(ax[i], base + (uint32_t)((wm * 32 + i * 16 + lrow) * ROWB_M
                                               + kk * 32 + lkb));
#pragma unroll
            for (int g = 0; g < 4; ++g) {
                const uint32_t bo = base + MATB_M
                    + (uint32_t)((wn * 64 + g * 16 + lrow) * ROWB_M + kk * 32 + lkb);
                uint32_t hh[4], hl[4];
                ldsm4(hh, bo);
                ldsm4(hl, bo + MATB_M);
#pragma unroll
                for (int i = 0; i < 2; ++i) {
                    float* d0 = acc[i][2 * g];
                    float* d1 = acc[i][2 * g + 1];
                    mma_f16(d0, ax[i], hh[0], hh[2]);
                    mma_f16(d0, ax[i], hl[0], hl[2]);
                    mma_f16(d1, ax[i], hh[1], hh[3]);
                    mma_f16(d1, ax[i], hl[1], hl[3]);
                }
            }
        }
        __syncthreads();
    }

    // ---- epilogue: part = dot(acc_row, x_row[J-block]) ----
    float* zbuf = (float*)smem;
    if (tid < MTILE) zbuf[tid] = 0.f;
    __syncthreads();

    float part[2][2] = {{0.f, 0.f}, {0.f, 0.f}};
#pragma unroll
    for (int i = 0; i < 2; ++i)
#pragma unroll
        for (int h = 0; h < 2; ++h) {
            const int row = rblk + wm * 32 + i * 16 + (lane >> 2) + h * 8;
            const float* xr = x + (size_t)row * FEAT + J * 128 + wn * 64
                              + (lane & 3) * 2;
#pragma unroll
            for (int j = 0; j < 8; ++j) {
                const float2 xv = *(const float2*)(xr + j * 8);
                part[i][h] += acc[i][j][2 * h] * xv.x + acc[i][j][2 * h + 1] * xv.y;
            }
        }

#pragma unroll
    for (int m = 1; m < 4; m <<= 1)
#pragma unroll
        for (int i = 0; i < 2; ++i)
#pragma unroll
            for (int h = 0; h < 2; ++h)
                part[i][h] += __shfl_xor_sync(0xffffffffu, part[i][h], m);
    if ((lane & 3) == 0) {
#pragma unroll
        for (int i = 0; i < 2; ++i)
#pragma unroll
            for (int h = 0; h < 2; ++h)
                atomicAdd(&zbuf[wm * 32 + i * 16 + (lane >> 2) + h * 8], part[i][h]);
    }
    __syncthreads();
    if (tid < MTILE)
        g_zpart[grp][rblk + tid] = zbuf[tid];
}

// ================= final combine =================
__global__ void __launch_bounds__(256)
ffm_fin(const float* __restrict__ bias, float* __restrict__ out) {
    const int row = blockIdx.x * 256 + threadIdx.x;
    float zs = 0.f;
#pragma unroll
    for (int u = 0; u < NBLK; ++u) zs += g_zpart[u][row];
    const float z = 4.8828125e-4f * zs + g_lin[row] + bias[0];  // 0.5 * 2^-10
    out[row] = 1.f / (1.f + expf(-z));
}

// ================= launch =================
extern "C" void kernel_launch(void* const* d_in, const int* in_sizes, int n_in,
                              void* d_out, int out_size) {
    const float* x = (const float*)d_in[0];
    const float* w = (const float*)d_in[1];
    const float* b = (const float*)d_in[2];
    const float* v = (const float*)d_in[3];
    float* out = (float*)d_out;

    cudaFuncSetAttribute(prep_H,   cudaFuncAttributeMaxDynamicSharedMemorySize, SMEM_H);
    cudaFuncSetAttribute(ffm_main, cudaFuncAttributeMaxDynamicSharedMemorySize, SMEM_M);

    prep_all<<<FEAT + NB, 256>>>(v, x, w);
    prep_H<<<NHB, 256, SMEM_H>>>();
    conv_H<<<FEAT, 256>>>();
    ffm_main<<<NBLK * RBLKS, THREADS, SMEM_M>>>(x);
    ffm_fin<<<NB / 256, 256>>>(b, out);
}